// round 13
// baseline (speedup 1.0000x reference)
#include <cuda_runtime.h>
#include <cuda_bf16.h>
#include <math.h>
#include <cstdint>

// Problem constants
#define BB 16
#define SS 512
#define HH 128
#define TT 32
#define SC 64      // s-chunk (N of GEMM)
#define TW 128     // t-window (M of GEMM)
#define NC (SS/SC)
#define IGROUP 8   // i's per block (grid = 8*16*2 = 256 -> single wave)
#define NBLOCKS (NC*BB*(BB/IGROUP))   // 256

// smem byte offsets
#define SM_A    0           // K-window [128][128] bf16 = 32768
#define SM_B    32768       // Q tile double buffer: 2 x 16384
#define SM_KMW  65536       // 128 floats
#define SM_WT   66048       // 33 floats (pad to 160B)
#define SM_PART 66208       // [8][64] float2 = 4096
#define SM_S1Q  70304       // [IGROUP][64] float2 = 4096  (S1, qm)
#define SM_KSUM 74400       // 128 floats = 512
#define SM_FLAG 74912       // int (pad 32)
#define SMEM_TOTAL 74944

// ---------------- device scratch ----------------
__device__ float g_qn[BB*SS*HH];     // normalized queries (fp32)
__device__ float g_kn[BB*SS*HH];     // normalized keys (fp32)
__device__ uint4 g_qb[BB*SS*16];     // normalized queries, bf16, pre-swizzled 256B rows
__device__ uint4 g_kb[BB*SS*16];     // normalized keys, bf16, pre-swizzled
__device__ float g_ksum4[BB*4*HH];
__device__ float g_cnt4[BB*4*2];
__device__ float g_partial2[BB*BB*NC*2];
__device__ float g_wtab[TT+1];
__device__ int   g_done;

// ---------------- helpers ----------------
__device__ __forceinline__ uint32_t smem_u32(const void* p) {
    uint32_t a;
    asm("{ .reg .u64 t; cvta.to.shared.u64 t, %1; cvt.u32.u64 %0, t; }" : "=r"(a) : "l"(p));
    return a;
}

#define LDSM4(r0,r1,r2,r3,addr) \
    asm volatile("ldmatrix.sync.aligned.m8n8.x4.shared.b16 {%0,%1,%2,%3}, [%4];" \
        : "=r"(r0), "=r"(r1), "=r"(r2), "=r"(r3) : "r"(addr))

#define MMA16816(d, a0,a1,a2,a3, b0,b1) \
    asm volatile("mma.sync.aligned.m16n8k16.row.col.f32.bf16.bf16.f32 " \
        "{%0,%1,%2,%3}, {%4,%5,%6,%7}, {%8,%9}, {%0,%1,%2,%3};" \
        : "+f"((d)[0]), "+f"((d)[1]), "+f"((d)[2]), "+f"((d)[3]) \
        : "r"(a0), "r"(a1), "r"(a2), "r"(a3), "r"(b0), "r"(b1))

// ---------------- K1: L2-normalize; write fp32 + pre-swizzled bf16 ----------------
__global__ void k_norm(const float* __restrict__ qe, const float* __restrict__ ke) {
    if (blockIdx.x == 0 && threadIdx.x == 0) g_done = 0;   // reset completion counter
    int row  = blockIdx.x * 8 + (threadIdx.x >> 5);
    int lane = threadIdx.x & 31;
    const float* src; float* dst; uint2* bdst; int rloc;
    if (row < BB*SS) {
        src = qe + (size_t)row*HH; dst = g_qn + (size_t)row*HH;
        bdst = reinterpret_cast<uint2*>(g_qb) + (size_t)row*32; rloc = row;
    } else {
        int r = row - BB*SS;
        src = ke + (size_t)r*HH; dst = g_kn + (size_t)r*HH;
        bdst = reinterpret_cast<uint2*>(g_kb) + (size_t)r*32; rloc = r;
    }
    float4 v = reinterpret_cast<const float4*>(src)[lane];
    float ss = v.x*v.x + v.y*v.y + v.z*v.z + v.w*v.w;
    #pragma unroll
    for (int off = 16; off >= 1; off >>= 1) ss += __shfl_xor_sync(0xffffffffu, ss, off);
    float sc = 1.0f / fmaxf(sqrtf(ss), 1e-12f);
    v.x *= sc; v.y *= sc; v.z *= sc; v.w *= sc;
    reinterpret_cast<float4*>(dst)[lane] = v;
    __nv_bfloat162 p0 = __floats2bfloat162_rn(v.x, v.y);
    __nv_bfloat162 p1 = __floats2bfloat162_rn(v.z, v.w);
    uint2 w2 = make_uint2(*reinterpret_cast<uint32_t*>(&p0),
                          *reinterpret_cast<uint32_t*>(&p1));
    int ch = lane >> 1;
    int slot = (((ch ^ (rloc & 7)) << 1) | (lane & 1));
    bdst[slot] = w2;
}

// ---------------- K2: per-(j, quarter) masked key sums + count partials ----------------
__global__ void k_prep(const float* __restrict__ km, const float* __restrict__ qm) {
    __shared__ float kms[128];
    __shared__ float reda[4], redb[4];
    int b = blockIdx.x;
    int j = b >> 2, q = b & 3;
    int tid = threadIdx.x;
    int tbase = q * 128;
    float kmv = (km[j*SS + tbase + tid] > 0.999f) ? 1.0f : 0.0f;
    float qmv = qm[j*SS + tbase + tid];
    kms[tid] = kmv;
    __syncthreads();
    float acc = 0.0f;
    #pragma unroll 4
    for (int t = 0; t < 128; t++)
        acc += g_kn[((size_t)j*SS + tbase + t)*HH + tid] * kms[t];
    g_ksum4[(size_t)b*HH + tid] = acc;
    float a = kmv, b2 = qmv;
    #pragma unroll
    for (int off = 16; off >= 1; off >>= 1) {
        a  += __shfl_xor_sync(0xffffffffu, a, off);
        b2 += __shfl_xor_sync(0xffffffffu, b2, off);
    }
    if ((tid & 31) == 0) { reda[tid >> 5] = a; redb[tid >> 5] = b2; }
    __syncthreads();
    if (tid == 0) {
        g_cnt4[b*2 + 0] = reda[0]+reda[1]+reda[2]+reda[3];
        g_cnt4[b*2 + 1] = redb[0]+redb[1]+redb[2]+redb[3];
    }
    if (b == 0 && tid <= TT) g_wtab[tid] = expf(-0.5f * (float)tid);
}

// ---------------- K3: main banded kernel — fused S1, last-block final reduce ----------------
__global__ __launch_bounds__(256) void k_main(const float* __restrict__ qm,
                                              const float* __restrict__ km,
                                              float* __restrict__ out) {
    extern __shared__ char smem[];
    uint32_t sb = smem_u32(smem);
    int c = blockIdx.x, j = blockIdx.y, ig = blockIdx.z;
    int tid = threadIdx.x;
    int wid = tid >> 5, lane = tid & 31;
    int t0 = c*SC - TT;
    int s0 = c*SC;

    float* kmw = reinterpret_cast<float*>(smem + SM_KMW);
    float* wt  = reinterpret_cast<float*>(smem + SM_WT);
    float2* part = reinterpret_cast<float2*>(smem + SM_PART);   // [8][64]
    float2* s1q  = reinterpret_cast<float2*>(smem + SM_S1Q);    // [IGROUP][64]
    float* ksum = reinterpret_cast<float*>(smem + SM_KSUM);     // [128]

    // ---- phase A: stage K window, masks, w-table, ksum, Q buffer 0 ----
    for (int idx = tid; idx < TW*16; idx += 256) {
        int r = idx >> 4;
        int tg = t0 + r;
        uint4 v = make_uint4(0u, 0u, 0u, 0u);
        if (tg >= 0 && tg < SS)
            v = g_kb[((size_t)j*SS + tg)*16 + (idx & 15)];
        *reinterpret_cast<uint4*>(smem + SM_A + idx*16) = v;
    }
    if (tid < TW) { int tg = t0 + tid; kmw[tid] = (tg >= 0 && tg < SS) ? km[j*SS + tg] : 0.f; }
    if (tid < TT+1) wt[tid] = g_wtab[tid];
    if (tid >= 128) {   // ksum_j: threads 128..255 -> ksum[0..127]
        int hh = tid - 128;
        float v = 0.f;
        #pragma unroll
        for (int p = 0; p < 4; p++) v += g_ksum4[((size_t)j*4 + p)*HH + hh];
        ksum[hh] = v;
    }
    {
        int i0 = ig*IGROUP;
        for (int idx = tid; idx < SC*16; idx += 256)
            *reinterpret_cast<uint4*>(smem + SM_B + idx*16) =
                g_qb[((size_t)i0*SS + s0)*16 + idx];
    }
    __syncthreads();

    // ---- phase B: compute S1 for all (ii, s) on 256 threads (2 dots each) ----
    // s1q reads happen only after the loop's post-epilogue __syncthreads -> no sync needed here.
    for (int idx = tid; idx < IGROUP*SC; idx += 256) {
        int ii = idx >> 6, s = idx & 63;
        int i = ig*IGROUP + ii;
        const float4* qr = reinterpret_cast<const float4*>(
            &g_qn[((size_t)i*SS + s0 + s)*HH]);
        float s1 = 0.f;
        #pragma unroll 8
        for (int h4 = 0; h4 < 32; h4++) {
            float4 qv = qr[h4];
            float4 kv = *reinterpret_cast<const float4*>(&ksum[h4*4]);
            s1 += qv.x*kv.x + qv.y*kv.y + qv.z*kv.z + qv.w*kv.w;
        }
        s1q[idx] = make_float2(s1, qm[i*SS + s0 + s]);
    }

    float kc_j = g_cnt4[(j*4+0)*2] + g_cnt4[(j*4+1)*2]
               + g_cnt4[(j*4+2)*2] + g_cnt4[(j*4+3)*2];
    int g_ = lane >> 2, t_ = lane & 3;
    int a_row = wid*16 + (lane & 15);
    int a_sel = lane >> 4;
    uint32_t a_rowoff = (uint32_t)(a_row * 256);
    int b_noff = ((lane >> 4) << 3) + (lane & 7);
    int b_sel = (lane >> 3) & 1;

    for (int ii = 0; ii < IGROUP; ii++) {
        int p = ii & 1;
        uint32_t bbase = sb + SM_B + (uint32_t)(p * 16384);

        // ---- GEMM ----
        float acc[8][4];
        #pragma unroll
        for (int nt = 0; nt < 8; nt++)
            #pragma unroll
            for (int x = 0; x < 4; x++) acc[nt][x] = 0.f;

        #pragma unroll
        for (int ks = 0; ks < 8; ks++) {
            int cb = 2*ks;
            uint32_t a_off = a_rowoff + (uint32_t)((((cb + a_sel) ^ (lane & 7)) << 4));
            uint32_t ah0,ah1,ah2,ah3;
            LDSM4(ah0,ah1,ah2,ah3, sb + SM_A + a_off);
            uint32_t b_chunk = (uint32_t)((((cb + b_sel) ^ (lane & 7)) << 4));
            #pragma unroll
            for (int np = 0; np < 4; np++) {
                uint32_t b_off = (uint32_t)((np*16 + b_noff) * 256) + b_chunk;
                uint32_t bh0,bh1,bh2,bh3;
                LDSM4(bh0,bh1,bh2,bh3, bbase + b_off);
                MMA16816(acc[2*np],   ah0,ah1,ah2,ah3, bh0,bh1);
                MMA16816(acc[2*np+1], ah0,ah1,ah2,ah3, bh2,bh3);
            }
        }

        // stage next Q into the other buffer (overlaps with epilogue below)
        if (ii + 1 < IGROUP) {
            int inext = ig*IGROUP + ii + 1;
            char* dst = smem + SM_B + (1-p)*16384;
            for (int idx = tid; idx < SC*16; idx += 256)
                *reinterpret_cast<uint4*>(dst + idx*16) =
                    g_qb[((size_t)inext*SS + s0)*16 + idx];
        }

        // ---- epilogue ----
        int r0 = wid*16 + g_;
        int r1 = r0 + 8;
        bool kok0 = kmw[r0] > 0.999f;
        bool kok1 = kmw[r1] > 0.999f;
        #pragma unroll
        for (int nt = 0; nt < 8; nt++) {
            int col0 = nt*8 + 2*t_;
            float gs0 = 0.f, gds0 = 0.f, gs1 = 0.f, gds1 = 0.f;
            {
                float d = acc[nt][0];
                int ad = r0 - col0 - TT; ad = (ad < 0) ? -ad : ad;
                if (ad <= TT && kok0) { float e = __expf(d * wt[ad]) - 1.0f; gs0 += e; gds0 += e*d; }
            }
            {
                float d = acc[nt][1];
                int ad = r0 - col0 - 1 - TT; ad = (ad < 0) ? -ad : ad;
                if (ad <= TT && kok0) { float e = __expf(d * wt[ad]) - 1.0f; gs1 += e; gds1 += e*d; }
            }
            {
                float d = acc[nt][2];
                int ad = r1 - col0 - TT; ad = (ad < 0) ? -ad : ad;
                if (ad <= TT && kok1) { float e = __expf(d * wt[ad]) - 1.0f; gs0 += e; gds0 += e*d; }
            }
            {
                float d = acc[nt][3];
                int ad = r1 - col0 - 1 - TT; ad = (ad < 0) ? -ad : ad;
                if (ad <= TT && kok1) { float e = __expf(d * wt[ad]) - 1.0f; gs1 += e; gds1 += e*d; }
            }
            #pragma unroll
            for (int off = 4; off <= 16; off <<= 1) {
                gs0  += __shfl_xor_sync(0xffffffffu, gs0,  off);
                gds0 += __shfl_xor_sync(0xffffffffu, gds0, off);
                gs1  += __shfl_xor_sync(0xffffffffu, gs1,  off);
                gds1 += __shfl_xor_sync(0xffffffffu, gds1, off);
            }
            if (g_ == 0) {
                part[wid*64 + col0]     = make_float2(gs0, gds0);
                part[wid*64 + col0 + 1] = make_float2(gs1, gds1);
            }
        }
        __syncthreads();

        // final: threads 0-63 own s; sum all 8 warps; write partials directly
        if (tid < 64) {
            int s = tid;
            float G = 0.f, Gd = 0.f;
            #pragma unroll
            for (int w = 0; w < 8; w++) {
                float2 p2 = part[w*64 + s];
                G += p2.x; Gd += p2.y;
            }
            float2 sq = s1q[ii*64 + s];
            float Z  = kc_j + G;
            float Nm = sq.x + Gd;
            float local = sq.y * ((Z > 1e-12f) ? (Nm / Z) : 0.f);
            #pragma unroll
            for (int off = 16; off >= 1; off >>= 1)
                local += __shfl_xor_sync(0xffffffffu, local, off);
            if (lane == 0) {
                int i = ig*IGROUP + ii;
                g_partial2[(((size_t)i*BB + j)*NC + c)*2 + wid] = local;
            }
        }
        __syncthreads();   // part free + Q buffer ready for next ii
    }

    // ---- completion: last block reduces g_partial2 into out ----
    if (tid == 0) {
        __threadfence();
        int old = atomicAdd(&g_done, 1);
        *reinterpret_cast<int*>(smem + SM_FLAG) = (old == NBLOCKS - 1) ? 1 : 0;
    }
    __syncthreads();
    if (*reinterpret_cast<int*>(smem + SM_FLAG)) {
        __threadfence();
        int t = tid;                 // 256 = (i,j)
        int i = t >> 4;
        float sacc = 0.f;
        #pragma unroll
        for (int cc = 0; cc < NC; cc++)
            sacc += g_partial2[((size_t)t*NC + cc)*2 + 0]
                  + g_partial2[((size_t)t*NC + cc)*2 + 1];
        float qd = 0.f;
        #pragma unroll
        for (int p = 0; p < 4; p++) qd += g_cnt4[(i*4+p)*2 + 1];
        out[t] = sacc / fmaxf(qd, 1.0f);
    }
}

// ---------------- launch ----------------
extern "C" void kernel_launch(void* const* d_in, const int* in_sizes, int n_in,
                              void* d_out, int out_size) {
    const float* qe = (const float*)d_in[0];
    const float* ke = (const float*)d_in[1];
    const float* qm = (const float*)d_in[2];
    const float* km = (const float*)d_in[3];
    float* out = (float*)d_out;

    cudaFuncSetAttribute(k_main, cudaFuncAttributeMaxDynamicSharedMemorySize, SMEM_TOTAL);

    k_norm <<<(2*BB*SS)/8, 256>>>(qe, ke);
    k_prep <<<BB*4, 128>>>(km, qm);
    k_main <<<dim3(NC, BB, BB/IGROUP), 256, SMEM_TOTAL>>>(qm, km, out);
}

// round 14
// speedup vs baseline: 1.1368x; 1.1368x over previous
#include <cuda_runtime.h>
#include <cuda_bf16.h>
#include <math.h>
#include <cstdint>

// Problem constants
#define BB 16
#define SS 512
#define HH 128
#define TT 32
#define SC 64      // s-chunk (N of GEMM)
#define TW 128     // t-window (M of GEMM)
#define NC (SS/SC)
#define IGROUP 8   // i's per block (grid = 8*16*2 = 256 -> single wave)
#define NBLOCKS (NC*BB*(BB/IGROUP))   // 256

// smem byte offsets
#define SM_A    0           // K-window [128][128] bf16 = 32768
#define SM_B    32768       // Q tile double buffer: 2 x 16384
#define SM_KMW  65536       // 128 floats
#define SM_WT   66048       // 33 floats (pad to 160B)
#define SM_PART 66208       // [8][64] float2 = 4096
#define SM_S1Q  70304       // [IGROUP][64] float2 = 4096  (S1, qm)
#define SM_FLAG 74400       // int (pad 32)
#define SMEM_TOTAL 74432

// ---------------- device scratch ----------------
__device__ float g_qn[BB*SS*HH];     // normalized queries (fp32)
__device__ float g_kn[BB*SS*HH];     // normalized keys (fp32)
__device__ uint4 g_qb[BB*SS*16];     // normalized queries, bf16, pre-swizzled 256B rows
__device__ uint4 g_kb[BB*SS*16];     // normalized keys, bf16, pre-swizzled
__device__ float g_ksum4[BB*4*HH];
__device__ float g_cnt4[BB*4*2];
__device__ float g_kcnt[BB];
__device__ float g_qdenom[BB];
__device__ float g_S1[BB*BB*SS];
__device__ float g_partial2[BB*BB*NC*2];
__device__ float g_wtab[TT+1];
__device__ int   g_done;

// ---------------- helpers ----------------
__device__ __forceinline__ uint32_t smem_u32(const void* p) {
    uint32_t a;
    asm("{ .reg .u64 t; cvta.to.shared.u64 t, %1; cvt.u32.u64 %0, t; }" : "=r"(a) : "l"(p));
    return a;
}

#define LDSM4(r0,r1,r2,r3,addr) \
    asm volatile("ldmatrix.sync.aligned.m8n8.x4.shared.b16 {%0,%1,%2,%3}, [%4];" \
        : "=r"(r0), "=r"(r1), "=r"(r2), "=r"(r3) : "r"(addr))

#define MMA16816(d, a0,a1,a2,a3, b0,b1) \
    asm volatile("mma.sync.aligned.m16n8k16.row.col.f32.bf16.bf16.f32 " \
        "{%0,%1,%2,%3}, {%4,%5,%6,%7}, {%8,%9}, {%0,%1,%2,%3};" \
        : "+f"((d)[0]), "+f"((d)[1]), "+f"((d)[2]), "+f"((d)[3]) \
        : "r"(a0), "r"(a1), "r"(a2), "r"(a3), "r"(b0), "r"(b1))

// ---------------- K1: L2-normalize; write fp32 + pre-swizzled bf16 ----------------
__global__ void k_norm(const float* __restrict__ qe, const float* __restrict__ ke) {
    if (blockIdx.x == 0 && threadIdx.x == 0) g_done = 0;   // reset completion counter
    int row  = blockIdx.x * 8 + (threadIdx.x >> 5);
    int lane = threadIdx.x & 31;
    const float* src; float* dst; uint2* bdst; int rloc;
    if (row < BB*SS) {
        src = qe + (size_t)row*HH; dst = g_qn + (size_t)row*HH;
        bdst = reinterpret_cast<uint2*>(g_qb) + (size_t)row*32; rloc = row;
    } else {
        int r = row - BB*SS;
        src = ke + (size_t)r*HH; dst = g_kn + (size_t)r*HH;
        bdst = reinterpret_cast<uint2*>(g_kb) + (size_t)r*32; rloc = r;
    }
    float4 v = reinterpret_cast<const float4*>(src)[lane];
    float ss = v.x*v.x + v.y*v.y + v.z*v.z + v.w*v.w;
    #pragma unroll
    for (int off = 16; off >= 1; off >>= 1) ss += __shfl_xor_sync(0xffffffffu, ss, off);
    float sc = 1.0f / fmaxf(sqrtf(ss), 1e-12f);
    v.x *= sc; v.y *= sc; v.z *= sc; v.w *= sc;
    reinterpret_cast<float4*>(dst)[lane] = v;
    __nv_bfloat162 p0 = __floats2bfloat162_rn(v.x, v.y);
    __nv_bfloat162 p1 = __floats2bfloat162_rn(v.z, v.w);
    uint2 w2 = make_uint2(*reinterpret_cast<uint32_t*>(&p0),
                          *reinterpret_cast<uint32_t*>(&p1));
    int ch = lane >> 1;
    int slot = (((ch ^ (rloc & 7)) << 1) | (lane & 1));
    bdst[slot] = w2;
}

// ---------------- K2: per-(j, quarter) masked key sums + count partials ----------------
__global__ void k_prep(const float* __restrict__ km, const float* __restrict__ qm) {
    __shared__ float kms[128];
    __shared__ float reda[4], redb[4];
    int b = blockIdx.x;
    int j = b >> 2, q = b & 3;
    int tid = threadIdx.x;
    int tbase = q * 128;
    float kmv = (km[j*SS + tbase + tid] > 0.999f) ? 1.0f : 0.0f;
    float qmv = qm[j*SS + tbase + tid];
    kms[tid] = kmv;
    __syncthreads();
    float acc = 0.0f;
    #pragma unroll 4
    for (int t = 0; t < 128; t++)
        acc += g_kn[((size_t)j*SS + tbase + t)*HH + tid] * kms[t];
    g_ksum4[(size_t)b*HH + tid] = acc;
    float a = kmv, b2 = qmv;
    #pragma unroll
    for (int off = 16; off >= 1; off >>= 1) {
        a  += __shfl_xor_sync(0xffffffffu, a, off);
        b2 += __shfl_xor_sync(0xffffffffu, b2, off);
    }
    if ((tid & 31) == 0) { reda[tid >> 5] = a; redb[tid >> 5] = b2; }
    __syncthreads();
    if (tid == 0) {
        g_cnt4[b*2 + 0] = reda[0]+reda[1]+reda[2]+reda[3];
        g_cnt4[b*2 + 1] = redb[0]+redb[1]+redb[2]+redb[3];
    }
    if (b == 0 && tid <= TT) g_wtab[tid] = expf(-0.5f * (float)tid);
}

// ---------------- K3: S1 + finalize counts ----------------
__global__ void k_s1() {
    __shared__ float ks[BB*HH];
    int tid = threadIdx.x;
    for (int x = tid; x < BB*HH; x += 256) {
        int jj = x >> 7, hh = x & (HH-1);
        float v = 0.f;
        #pragma unroll
        for (int p = 0; p < 4; p++) v += g_ksum4[((size_t)jj*4 + p)*HH + hh];
        ks[x] = v;
    }
    if (blockIdx.x == 0 && tid < BB) {
        float a = 0.f, b = 0.f;
        #pragma unroll
        for (int p = 0; p < 4; p++) { a += g_cnt4[(tid*4+p)*2+0]; b += g_cnt4[(tid*4+p)*2+1]; }
        g_kcnt[tid]   = a;
        g_qdenom[tid] = fmaxf(b, 1.0f);
    }
    __syncthreads();
    int w = tid >> 5, lane = tid & 31;
    int row = blockIdx.x * 8 + w;
    int i = row >> 9, s = row & (SS-1);
    float4 q = *reinterpret_cast<const float4*>(&g_qn[(size_t)row*HH + lane*4]);
    #pragma unroll
    for (int j = 0; j < BB; j++) {
        float4 k4 = *reinterpret_cast<const float4*>(&ks[j*HH + lane*4]);
        float p = q.x*k4.x + q.y*k4.y + q.z*k4.z + q.w*k4.w;
        #pragma unroll
        for (int off = 16; off >= 1; off >>= 1) p += __shfl_xor_sync(0xffffffffu, p, off);
        if (lane == 0) g_S1[((size_t)i*BB + j)*SS + s] = p;
    }
}

// ---------------- K4: main banded kernel — single wave; last block writes out ----------------
__global__ __launch_bounds__(256) void k_main(const float* __restrict__ qm,
                                              const float* __restrict__ km,
                                              float* __restrict__ out) {
    extern __shared__ char smem[];
    uint32_t sb = smem_u32(smem);
    int c = blockIdx.x, j = blockIdx.y, ig = blockIdx.z;
    int tid = threadIdx.x;
    int wid = tid >> 5, lane = tid & 31;
    int t0 = c*SC - TT;
    int s0 = c*SC;

    float* kmw = reinterpret_cast<float*>(smem + SM_KMW);
    float* wt  = reinterpret_cast<float*>(smem + SM_WT);
    float2* part = reinterpret_cast<float2*>(smem + SM_PART);   // [8][64]
    float2* s1q  = reinterpret_cast<float2*>(smem + SM_S1Q);    // [IGROUP][64]

    // stage K-window: verbatim copy (pre-swizzled), zero-pad out-of-range rows
    for (int idx = tid; idx < TW*16; idx += 256) {
        int r = idx >> 4;
        int tg = t0 + r;
        uint4 v = make_uint4(0u, 0u, 0u, 0u);
        if (tg >= 0 && tg < SS)
            v = g_kb[((size_t)j*SS + tg)*16 + (idx & 15)];
        *reinterpret_cast<uint4*>(smem + SM_A + idx*16) = v;
    }
    if (tid < TW) { int tg = t0 + tid; kmw[tid] = (tg >= 0 && tg < SS) ? km[j*SS + tg] : 0.f; }
    if (tid >= 128 && tid <= 128+TT) wt[tid-128] = g_wtab[tid-128];
    // prefetch S1 + qm for all IGROUP i's
    for (int idx = tid; idx < IGROUP*SC; idx += 256) {
        int ii = idx >> 6, s = idx & 63;
        int i = ig*IGROUP + ii;
        s1q[idx] = make_float2(g_S1[((size_t)i*BB + j)*SS + s0 + s],
                               qm[i*SS + s0 + s]);
    }
    // stage Q buffer 0
    {
        int i0 = ig*IGROUP;
        for (int idx = tid; idx < SC*16; idx += 256)
            *reinterpret_cast<uint4*>(smem + SM_B + idx*16) =
                g_qb[((size_t)i0*SS + s0)*16 + idx];
    }
    __syncthreads();

    float kc_j = g_kcnt[j];
    int g_ = lane >> 2, t_ = lane & 3;
    int a_row = wid*16 + (lane & 15);
    int a_sel = lane >> 4;
    uint32_t a_rowoff = (uint32_t)(a_row * 256);
    int b_noff = ((lane >> 4) << 3) + (lane & 7);
    int b_sel = (lane >> 3) & 1;

    for (int ii = 0; ii < IGROUP; ii++) {
        int p = ii & 1;
        uint32_t bbase = sb + SM_B + (uint32_t)(p * 16384);

        // ---- GEMM ----
        float acc[8][4];
        #pragma unroll
        for (int nt = 0; nt < 8; nt++)
            #pragma unroll
            for (int x = 0; x < 4; x++) acc[nt][x] = 0.f;

        #pragma unroll
        for (int ks = 0; ks < 8; ks++) {
            int cb = 2*ks;
            uint32_t a_off = a_rowoff + (uint32_t)((((cb + a_sel) ^ (lane & 7)) << 4));
            uint32_t ah0,ah1,ah2,ah3;
            LDSM4(ah0,ah1,ah2,ah3, sb + SM_A + a_off);
            uint32_t b_chunk = (uint32_t)((((cb + b_sel) ^ (lane & 7)) << 4));
            #pragma unroll
            for (int np = 0; np < 4; np++) {
                uint32_t b_off = (uint32_t)((np*16 + b_noff) * 256) + b_chunk;
                uint32_t bh0,bh1,bh2,bh3;
                LDSM4(bh0,bh1,bh2,bh3, bbase + b_off);
                MMA16816(acc[2*np],   ah0,ah1,ah2,ah3, bh0,bh1);
                MMA16816(acc[2*np+1], ah0,ah1,ah2,ah3, bh2,bh3);
            }
        }

        // stage next Q into the other buffer (overlaps with epilogue below)
        if (ii + 1 < IGROUP) {
            int inext = ig*IGROUP + ii + 1;
            char* dst = smem + SM_B + (1-p)*16384;
            for (int idx = tid; idx < SC*16; idx += 256)
                *reinterpret_cast<uint4*>(dst + idx*16) =
                    g_qb[((size_t)inext*SS + s0)*16 + idx];
        }

        // ---- epilogue ----
        int r0 = wid*16 + g_;
        int r1 = r0 + 8;
        bool kok0 = kmw[r0] > 0.999f;
        bool kok1 = kmw[r1] > 0.999f;
        #pragma unroll
        for (int nt = 0; nt < 8; nt++) {
            int col0 = nt*8 + 2*t_;
            float gs0 = 0.f, gds0 = 0.f, gs1 = 0.f, gds1 = 0.f;
            {
                float d = acc[nt][0];
                int ad = r0 - col0 - TT; ad = (ad < 0) ? -ad : ad;
                if (ad <= TT && kok0) { float e = __expf(d * wt[ad]) - 1.0f; gs0 += e; gds0 += e*d; }
            }
            {
                float d = acc[nt][1];
                int ad = r0 - col0 - 1 - TT; ad = (ad < 0) ? -ad : ad;
                if (ad <= TT && kok0) { float e = __expf(d * wt[ad]) - 1.0f; gs1 += e; gds1 += e*d; }
            }
            {
                float d = acc[nt][2];
                int ad = r1 - col0 - TT; ad = (ad < 0) ? -ad : ad;
                if (ad <= TT && kok1) { float e = __expf(d * wt[ad]) - 1.0f; gs0 += e; gds0 += e*d; }
            }
            {
                float d = acc[nt][3];
                int ad = r1 - col0 - 1 - TT; ad = (ad < 0) ? -ad : ad;
                if (ad <= TT && kok1) { float e = __expf(d * wt[ad]) - 1.0f; gs1 += e; gds1 += e*d; }
            }
            #pragma unroll
            for (int off = 4; off <= 16; off <<= 1) {
                gs0  += __shfl_xor_sync(0xffffffffu, gs0,  off);
                gds0 += __shfl_xor_sync(0xffffffffu, gds0, off);
                gs1  += __shfl_xor_sync(0xffffffffu, gs1,  off);
                gds1 += __shfl_xor_sync(0xffffffffu, gds1, off);
            }
            if (g_ == 0) {
                part[wid*64 + col0]     = make_float2(gs0, gds0);
                part[wid*64 + col0 + 1] = make_float2(gs1, gds1);
            }
        }
        __syncthreads();

        // final: threads 0-63 own s; sum all 8 warps; write partials directly
        if (tid < 64) {
            int s = tid;
            float G = 0.f, Gd = 0.f;
            #pragma unroll
            for (int w = 0; w < 8; w++) {
                float2 p2 = part[w*64 + s];
                G += p2.x; Gd += p2.y;
            }
            float2 sq = s1q[ii*64 + s];
            float Z  = kc_j + G;
            float Nm = sq.x + Gd;
            float local = sq.y * ((Z > 1e-12f) ? (Nm / Z) : 0.f);
            #pragma unroll
            for (int off = 16; off >= 1; off >>= 1)
                local += __shfl_xor_sync(0xffffffffu, local, off);
            if (lane == 0) {
                int i = ig*IGROUP + ii;
                g_partial2[(((size_t)i*BB + j)*NC + c)*2 + wid] = local;
            }
        }
        __syncthreads();   // part free + Q buffer ready for next ii
    }

    // ---- completion: last block reduces g_partial2 into out ----
    if (tid == 0) {
        __threadfence();
        int old = atomicAdd(&g_done, 1);
        *reinterpret_cast<int*>(smem + SM_FLAG) = (old == NBLOCKS - 1) ? 1 : 0;
    }
    __syncthreads();
    if (*reinterpret_cast<int*>(smem + SM_FLAG)) {
        __threadfence();
        int t = tid;                 // 256 = (i,j)
        float sacc = 0.f;
        #pragma unroll
        for (int cc = 0; cc < NC; cc++)
            sacc += g_partial2[((size_t)t*NC + cc)*2 + 0]
                  + g_partial2[((size_t)t*NC + cc)*2 + 1];
        out[t] = sacc / g_qdenom[t >> 4];
    }
}

// ---------------- launch ----------------
extern "C" void kernel_launch(void* const* d_in, const int* in_sizes, int n_in,
                              void* d_out, int out_size) {
    const float* qe = (const float*)d_in[0];
    const float* ke = (const float*)d_in[1];
    const float* qm = (const float*)d_in[2];
    const float* km = (const float*)d_in[3];
    float* out = (float*)d_out;

    cudaFuncSetAttribute(k_main, cudaFuncAttributeMaxDynamicSharedMemorySize, SMEM_TOTAL);

    k_norm <<<(2*BB*SS)/8, 256>>>(qe, ke);
    k_prep <<<BB*4, 128>>>(km, qm);
    k_s1   <<<(BB*SS)/8, 256>>>();
    k_main <<<dim3(NC, BB, BB/IGROUP), 256, SMEM_TOTAL>>>(qm, km, out);
}

// round 15
// speedup vs baseline: 1.1718x; 1.0308x over previous
#include <cuda_runtime.h>
#include <cuda_bf16.h>
#include <math.h>
#include <cstdint>

// Problem constants
#define BB 16
#define SS 512
#define HH 128
#define TT 32
#define SC 64      // s-chunk (N of GEMM)
#define TW 128     // t-window (M of GEMM)
#define NC (SS/SC)
#define IGROUP 8   // i's per block (grid = 8*16*2 = 256 -> single wave)
#define NBLOCKS (NC*BB*(BB/IGROUP))   // 256

// smem byte offsets
#define SM_A    0           // K-window [128][128] bf16 = 32768
#define SM_B    32768       // Q tile double buffer: 2 x 16384
#define SM_KMW  65536       // 128 floats
#define SM_WT   66048       // 33 floats (pad to 160B)
#define SM_PART 66208       // [IGROUP][8][64] float2 = 32768
#define SM_S1Q  98976       // [IGROUP][64] float2 = 4096  (S1, qm)
#define SM_FLAG 103072      // int (pad 32)
#define SMEM_TOTAL 103104

// ---------------- device scratch ----------------
__device__ float g_qn[BB*SS*HH];     // normalized queries (fp32)
__device__ float g_kn[BB*SS*HH];     // normalized keys (fp32)
__device__ uint4 g_qb[BB*SS*16];     // normalized queries, bf16, pre-swizzled 256B rows
__device__ uint4 g_kb[BB*SS*16];     // normalized keys, bf16, pre-swizzled
__device__ float g_ksum4[BB*4*HH];
__device__ float g_cnt4[BB*4*2];
__device__ float g_kcnt[BB];
__device__ float g_qdenom[BB];
__device__ float g_S1[BB*BB*SS];
__device__ float g_partial2[BB*BB*NC*2];
__device__ float g_wtab[TT+1];
__device__ int   g_done;

// ---------------- helpers ----------------
__device__ __forceinline__ uint32_t smem_u32(const void* p) {
    uint32_t a;
    asm("{ .reg .u64 t; cvta.to.shared.u64 t, %1; cvt.u32.u64 %0, t; }" : "=r"(a) : "l"(p));
    return a;
}

#define LDSM4(r0,r1,r2,r3,addr) \
    asm volatile("ldmatrix.sync.aligned.m8n8.x4.shared.b16 {%0,%1,%2,%3}, [%4];" \
        : "=r"(r0), "=r"(r1), "=r"(r2), "=r"(r3) : "r"(addr))

#define MMA16816(d, a0,a1,a2,a3, b0,b1) \
    asm volatile("mma.sync.aligned.m16n8k16.row.col.f32.bf16.bf16.f32 " \
        "{%0,%1,%2,%3}, {%4,%5,%6,%7}, {%8,%9}, {%0,%1,%2,%3};" \
        : "+f"((d)[0]), "+f"((d)[1]), "+f"((d)[2]), "+f"((d)[3]) \
        : "r"(a0), "r"(a1), "r"(a2), "r"(a3), "r"(b0), "r"(b1))

// ---------------- K1: L2-normalize; write fp32 + pre-swizzled bf16 ----------------
__global__ void k_norm(const float* __restrict__ qe, const float* __restrict__ ke) {
    if (blockIdx.x == 0 && threadIdx.x == 0) g_done = 0;   // reset completion counter
    int row  = blockIdx.x * 8 + (threadIdx.x >> 5);
    int lane = threadIdx.x & 31;
    const float* src; float* dst; uint2* bdst; int rloc;
    if (row < BB*SS) {
        src = qe + (size_t)row*HH; dst = g_qn + (size_t)row*HH;
        bdst = reinterpret_cast<uint2*>(g_qb) + (size_t)row*32; rloc = row;
    } else {
        int r = row - BB*SS;
        src = ke + (size_t)r*HH; dst = g_kn + (size_t)r*HH;
        bdst = reinterpret_cast<uint2*>(g_kb) + (size_t)r*32; rloc = r;
    }
    float4 v = reinterpret_cast<const float4*>(src)[lane];
    float ss = v.x*v.x + v.y*v.y + v.z*v.z + v.w*v.w;
    #pragma unroll
    for (int off = 16; off >= 1; off >>= 1) ss += __shfl_xor_sync(0xffffffffu, ss, off);
    float sc = 1.0f / fmaxf(sqrtf(ss), 1e-12f);
    v.x *= sc; v.y *= sc; v.z *= sc; v.w *= sc;
    reinterpret_cast<float4*>(dst)[lane] = v;
    __nv_bfloat162 p0 = __floats2bfloat162_rn(v.x, v.y);
    __nv_bfloat162 p1 = __floats2bfloat162_rn(v.z, v.w);
    uint2 w2 = make_uint2(*reinterpret_cast<uint32_t*>(&p0),
                          *reinterpret_cast<uint32_t*>(&p1));
    int ch = lane >> 1;
    int slot = (((ch ^ (rloc & 7)) << 1) | (lane & 1));
    bdst[slot] = w2;
}

// ---------------- K2: per-(j, quarter) masked key sums + count partials ----------------
__global__ void k_prep(const float* __restrict__ km, const float* __restrict__ qm) {
    __shared__ float kms[128];
    __shared__ float reda[4], redb[4];
    int b = blockIdx.x;
    int j = b >> 2, q = b & 3;
    int tid = threadIdx.x;
    int tbase = q * 128;
    float kmv = (km[j*SS + tbase + tid] > 0.999f) ? 1.0f : 0.0f;
    float qmv = qm[j*SS + tbase + tid];
    kms[tid] = kmv;
    __syncthreads();
    float acc = 0.0f;
    #pragma unroll 4
    for (int t = 0; t < 128; t++)
        acc += g_kn[((size_t)j*SS + tbase + t)*HH + tid] * kms[t];
    g_ksum4[(size_t)b*HH + tid] = acc;
    float a = kmv, b2 = qmv;
    #pragma unroll
    for (int off = 16; off >= 1; off >>= 1) {
        a  += __shfl_xor_sync(0xffffffffu, a, off);
        b2 += __shfl_xor_sync(0xffffffffu, b2, off);
    }
    if ((tid & 31) == 0) { reda[tid >> 5] = a; redb[tid >> 5] = b2; }
    __syncthreads();
    if (tid == 0) {
        g_cnt4[b*2 + 0] = reda[0]+reda[1]+reda[2]+reda[3];
        g_cnt4[b*2 + 1] = redb[0]+redb[1]+redb[2]+redb[3];
    }
    if (b == 0 && tid <= TT) g_wtab[tid] = expf(-0.5f * (float)tid);
}

// ---------------- K3: S1 + finalize counts ----------------
__global__ void k_s1() {
    __shared__ float ks[BB*HH];
    int tid = threadIdx.x;
    for (int x = tid; x < BB*HH; x += 256) {
        int jj = x >> 7, hh = x & (HH-1);
        float v = 0.f;
        #pragma unroll
        for (int p = 0; p < 4; p++) v += g_ksum4[((size_t)jj*4 + p)*HH + hh];
        ks[x] = v;
    }
    if (blockIdx.x == 0 && tid < BB) {
        float a = 0.f, b = 0.f;
        #pragma unroll
        for (int p = 0; p < 4; p++) { a += g_cnt4[(tid*4+p)*2+0]; b += g_cnt4[(tid*4+p)*2+1]; }
        g_kcnt[tid]   = a;
        g_qdenom[tid] = fmaxf(b, 1.0f);
    }
    __syncthreads();
    int w = tid >> 5, lane = tid & 31;
    int row = blockIdx.x * 8 + w;
    int i = row >> 9, s = row & (SS-1);
    float4 q = *reinterpret_cast<const float4*>(&g_qn[(size_t)row*HH + lane*4]);
    #pragma unroll
    for (int j = 0; j < BB; j++) {
        float4 k4 = *reinterpret_cast<const float4*>(&ks[j*HH + lane*4]);
        float p = q.x*k4.x + q.y*k4.y + q.z*k4.z + q.w*k4.w;
        #pragma unroll
        for (int off = 16; off >= 1; off >>= 1) p += __shfl_xor_sync(0xffffffffu, p, off);
        if (lane == 0) g_S1[((size_t)i*BB + j)*SS + s] = p;
    }
}

// ---------------- K4: main banded kernel — 1 sync/ii, deferred final ----------------
__global__ __launch_bounds__(256) void k_main(const float* __restrict__ qm,
                                              const float* __restrict__ km,
                                              float* __restrict__ out) {
    extern __shared__ char smem[];
    uint32_t sb = smem_u32(smem);
    int c = blockIdx.x, j = blockIdx.y, ig = blockIdx.z;
    int tid = threadIdx.x;
    int wid = tid >> 5, lane = tid & 31;
    int t0 = c*SC - TT;
    int s0 = c*SC;

    float* kmw = reinterpret_cast<float*>(smem + SM_KMW);
    float* wt  = reinterpret_cast<float*>(smem + SM_WT);
    float2* part = reinterpret_cast<float2*>(smem + SM_PART);   // [IGROUP][8][64]
    float2* s1q  = reinterpret_cast<float2*>(smem + SM_S1Q);    // [IGROUP][64]

    // stage K-window: verbatim copy (pre-swizzled), zero-pad out-of-range rows
    for (int idx = tid; idx < TW*16; idx += 256) {
        int r = idx >> 4;
        int tg = t0 + r;
        uint4 v = make_uint4(0u, 0u, 0u, 0u);
        if (tg >= 0 && tg < SS)
            v = g_kb[((size_t)j*SS + tg)*16 + (idx & 15)];
        *reinterpret_cast<uint4*>(smem + SM_A + idx*16) = v;
    }
    if (tid < TW) { int tg = t0 + tid; kmw[tid] = (tg >= 0 && tg < SS) ? km[j*SS + tg] : 0.f; }
    if (tid >= 128 && tid <= 128+TT) wt[tid-128] = g_wtab[tid-128];
    // prefetch S1 + qm for all IGROUP i's
    for (int idx = tid; idx < IGROUP*SC; idx += 256) {
        int ii = idx >> 6, s = idx & 63;
        int i = ig*IGROUP + ii;
        s1q[idx] = make_float2(g_S1[((size_t)i*BB + j)*SS + s0 + s],
                               qm[i*SS + s0 + s]);
    }
    // stage Q buffer 0
    {
        int i0 = ig*IGROUP;
        for (int idx = tid; idx < SC*16; idx += 256)
            *reinterpret_cast<uint4*>(smem + SM_B + idx*16) =
                g_qb[((size_t)i0*SS + s0)*16 + idx];
    }
    __syncthreads();

    float kc_j = g_kcnt[j];
    int g_ = lane >> 2, t_ = lane & 3;
    int a_row = wid*16 + (lane & 15);
    int a_sel = lane >> 4;
    uint32_t a_rowoff = (uint32_t)(a_row * 256);
    int b_noff = ((lane >> 4) << 3) + (lane & 7);
    int b_sel = (lane >> 3) & 1;

    for (int ii = 0; ii < IGROUP; ii++) {
        int p = ii & 1;
        uint32_t bbase = sb + SM_B + (uint32_t)(p * 16384);

        // ---- GEMM ----
        float acc[8][4];
        #pragma unroll
        for (int nt = 0; nt < 8; nt++)
            #pragma unroll
            for (int x = 0; x < 4; x++) acc[nt][x] = 0.f;

        #pragma unroll
        for (int ks = 0; ks < 8; ks++) {
            int cb = 2*ks;
            uint32_t a_off = a_rowoff + (uint32_t)((((cb + a_sel) ^ (lane & 7)) << 4));
            uint32_t ah0,ah1,ah2,ah3;
            LDSM4(ah0,ah1,ah2,ah3, sb + SM_A + a_off);
            uint32_t b_chunk = (uint32_t)((((cb + b_sel) ^ (lane & 7)) << 4));
            #pragma unroll
            for (int np = 0; np < 4; np++) {
                uint32_t b_off = (uint32_t)((np*16 + b_noff) * 256) + b_chunk;
                uint32_t bh0,bh1,bh2,bh3;
                LDSM4(bh0,bh1,bh2,bh3, bbase + b_off);
                MMA16816(acc[2*np],   ah0,ah1,ah2,ah3, bh0,bh1);
                MMA16816(acc[2*np+1], ah0,ah1,ah2,ah3, bh2,bh3);
            }
        }

        // stage next Q into the other buffer (overlaps with epilogue below)
        if (ii + 1 < IGROUP) {
            int inext = ig*IGROUP + ii + 1;
            char* dst = smem + SM_B + (1-p)*16384;
            for (int idx = tid; idx < SC*16; idx += 256)
                *reinterpret_cast<uint4*>(dst + idx*16) =
                    g_qb[((size_t)inext*SS + s0)*16 + idx];
        }

        // ---- epilogue (writes per-ii part region; no per-ii final) ----
        int r0 = wid*16 + g_;
        int r1 = r0 + 8;
        bool kok0 = kmw[r0] > 0.999f;
        bool kok1 = kmw[r1] > 0.999f;
        float2* pii = part + ii*512 + wid*64;
        #pragma unroll
        for (int nt = 0; nt < 8; nt++) {
            int col0 = nt*8 + 2*t_;
            float gs0 = 0.f, gds0 = 0.f, gs1 = 0.f, gds1 = 0.f;
            {
                float d = acc[nt][0];
                int ad = r0 - col0 - TT; ad = (ad < 0) ? -ad : ad;
                if (ad <= TT && kok0) { float e = __expf(d * wt[ad]) - 1.0f; gs0 += e; gds0 += e*d; }
            }
            {
                float d = acc[nt][1];
                int ad = r0 - col0 - 1 - TT; ad = (ad < 0) ? -ad : ad;
                if (ad <= TT && kok0) { float e = __expf(d * wt[ad]) - 1.0f; gs1 += e; gds1 += e*d; }
            }
            {
                float d = acc[nt][2];
                int ad = r1 - col0 - TT; ad = (ad < 0) ? -ad : ad;
                if (ad <= TT && kok1) { float e = __expf(d * wt[ad]) - 1.0f; gs0 += e; gds0 += e*d; }
            }
            {
                float d = acc[nt][3];
                int ad = r1 - col0 - 1 - TT; ad = (ad < 0) ? -ad : ad;
                if (ad <= TT && kok1) { float e = __expf(d * wt[ad]) - 1.0f; gs1 += e; gds1 += e*d; }
            }
            #pragma unroll
            for (int off = 4; off <= 16; off <<= 1) {
                gs0  += __shfl_xor_sync(0xffffffffu, gs0,  off);
                gds0 += __shfl_xor_sync(0xffffffffu, gds0, off);
                gs1  += __shfl_xor_sync(0xffffffffu, gs1,  off);
                gds1 += __shfl_xor_sync(0xffffffffu, gds1, off);
            }
            if (g_ == 0) {
                pii[col0]     = make_float2(gs0, gds0);
                pii[col0 + 1] = make_float2(gs1, gds1);
            }
        }
        __syncthreads();   // Q buffer ready for next GEMM (also orders staging)
    }

    // ---- deferred final: 512 (ii,s) items on 256 threads, 2 passes ----
    // (the loop's last __syncthreads ordered all part writes)
    #pragma unroll
    for (int pass = 0; pass < 2; pass++) {
        int idx = pass*256 + tid;
        int ii = idx >> 6, s = idx & 63;
        float G = 0.f, Gd = 0.f;
        #pragma unroll
        for (int w = 0; w < 8; w++) {
            float2 p2 = part[ii*512 + w*64 + s];
            G += p2.x; Gd += p2.y;
        }
        float2 sq = s1q[ii*64 + s];
        float Z  = kc_j + G;
        float Nm = sq.x + Gd;
        float local = sq.y * ((Z > 1e-12f) ? (Nm / Z) : 0.f);
        #pragma unroll
        for (int off = 16; off >= 1; off >>= 1)
            local += __shfl_xor_sync(0xffffffffu, local, off);
        if (lane == 0) {
            int i = ig*IGROUP + ii;
            g_partial2[(((size_t)i*BB + j)*NC + c)*2 + (wid & 1)] = local;
        }
    }

    // ---- completion: last block reduces g_partial2 into out ----
    if (tid == 0) {
        __threadfence();
        int old = atomicAdd(&g_done, 1);
        *reinterpret_cast<int*>(smem + SM_FLAG) = (old == NBLOCKS - 1) ? 1 : 0;
    }
    __syncthreads();
    if (*reinterpret_cast<int*>(smem + SM_FLAG)) {
        __threadfence();
        int t = tid;                 // 256 = (i,j)
        float sacc = 0.f;
        #pragma unroll
        for (int cc = 0; cc < NC; cc++)
            sacc += g_partial2[((size_t)t*NC + cc)*2 + 0]
                  + g_partial2[((size_t)t*NC + cc)*2 + 1];
        out[t] = sacc / g_qdenom[t >> 4];
    }
}

// ---------------- launch ----------------
extern "C" void kernel_launch(void* const* d_in, const int* in_sizes, int n_in,
                              void* d_out, int out_size) {
    const float* qe = (const float*)d_in[0];
    const float* ke = (const float*)d_in[1];
    const float* qm = (const float*)d_in[2];
    const float* km = (const float*)d_in[3];
    float* out = (float*)d_out;

    cudaFuncSetAttribute(k_main, cudaFuncAttributeMaxDynamicSharedMemorySize, SMEM_TOTAL);

    k_norm <<<(2*BB*SS)/8, 256>>>(qe, ke);
    k_prep <<<BB*4, 128>>>(km, qm);
    k_s1   <<<(BB*SS)/8, 256>>>();
    k_main <<<dim3(NC, BB, BB/IGROUP), 256, SMEM_TOTAL>>>(qm, km, out);
}

// round 16
// speedup vs baseline: 1.3189x; 1.1256x over previous
#include <cuda_runtime.h>
#include <cuda_bf16.h>
#include <math.h>
#include <cstdint>

// Problem constants
#define BB 16
#define SS 512
#define HH 128
#define TT 32
#define SC 64      // s-chunk (N of GEMM)
#define TW 128     // t-window (M of GEMM)
#define NC (SS/SC)
#define IGROUP 8   // i's per block (grid = 8*16*2 = 256 -> single wave)
#define NBLOCKS (NC*BB*(BB/IGROUP))   // 256

// smem byte offsets
#define SM_A    0           // K-window [128][128] bf16 = 32768
#define SM_B    32768       // Q tile double buffer: 2 x 16384
#define SM_KMW  65536       // 128 floats
#define SM_WT   66048       // 33 floats (pad to 160B)
#define SM_PART 66208       // [IGROUP][8][64] float2 = 32768
#define SM_S1Q  98976       // [IGROUP][64] float2 = 4096  (S1, qm)
#define SM_FLAG 103072      // int (pad 32)
#define SMEM_TOTAL 103104

// ---------------- device scratch ----------------
__device__ float g_qn[BB*SS*HH];     // normalized queries (fp32)
__device__ float g_kn[BB*SS*HH];     // normalized keys (fp32)
__device__ uint4 g_qb[BB*SS*16];     // normalized queries, bf16, pre-swizzled 256B rows
__device__ uint4 g_kb[BB*SS*16];     // normalized keys, bf16, pre-swizzled
__device__ float g_ksum4[BB*4*HH];
__device__ float g_cnt4[BB*4*2];
__device__ float g_kcnt[BB];
__device__ float g_qdenom[BB];
__device__ float g_S1[BB*BB*SS];
__device__ float g_partial2[BB*BB*NC*2];
__device__ float g_wtab[TT+1];
__device__ int   g_done;

// ---------------- helpers ----------------
__device__ __forceinline__ uint32_t smem_u32(const void* p) {
    uint32_t a;
    asm("{ .reg .u64 t; cvta.to.shared.u64 t, %1; cvt.u32.u64 %0, t; }" : "=r"(a) : "l"(p));
    return a;
}

#define LDSM4(r0,r1,r2,r3,addr) \
    asm volatile("ldmatrix.sync.aligned.m8n8.x4.shared.b16 {%0,%1,%2,%3}, [%4];" \
        : "=r"(r0), "=r"(r1), "=r"(r2), "=r"(r3) : "r"(addr))

#define MMA16816(d, a0,a1,a2,a3, b0,b1) \
    asm volatile("mma.sync.aligned.m16n8k16.row.col.f32.bf16.bf16.f32 " \
        "{%0,%1,%2,%3}, {%4,%5,%6,%7}, {%8,%9}, {%0,%1,%2,%3};" \
        : "+f"((d)[0]), "+f"((d)[1]), "+f"((d)[2]), "+f"((d)[3]) \
        : "r"(a0), "r"(a1), "r"(a2), "r"(a3), "r"(b0), "r"(b1))

// cp.async 16B with zero-fill when srcsize==0
__device__ __forceinline__ void cp_async16(uint32_t dst, const void* src, int srcsize) {
    asm volatile("cp.async.cg.shared.global [%0], [%1], 16, %2;"
                 :: "r"(dst), "l"(src), "r"(srcsize) : "memory");
}
#define CP_COMMIT() asm volatile("cp.async.commit_group;" ::: "memory")
#define CP_WAIT0()  asm volatile("cp.async.wait_group 0;" ::: "memory")

// ---------------- K1: L2-normalize; write fp32 + pre-swizzled bf16 ----------------
__global__ void k_norm(const float* __restrict__ qe, const float* __restrict__ ke) {
    if (blockIdx.x == 0 && threadIdx.x == 0) g_done = 0;   // reset completion counter
    int row  = blockIdx.x * 8 + (threadIdx.x >> 5);
    int lane = threadIdx.x & 31;
    const float* src; float* dst; uint2* bdst; int rloc;
    if (row < BB*SS) {
        src = qe + (size_t)row*HH; dst = g_qn + (size_t)row*HH;
        bdst = reinterpret_cast<uint2*>(g_qb) + (size_t)row*32; rloc = row;
    } else {
        int r = row - BB*SS;
        src = ke + (size_t)r*HH; dst = g_kn + (size_t)r*HH;
        bdst = reinterpret_cast<uint2*>(g_kb) + (size_t)r*32; rloc = r;
    }
    float4 v = reinterpret_cast<const float4*>(src)[lane];
    float ss = v.x*v.x + v.y*v.y + v.z*v.z + v.w*v.w;
    #pragma unroll
    for (int off = 16; off >= 1; off >>= 1) ss += __shfl_xor_sync(0xffffffffu, ss, off);
    float sc = 1.0f / fmaxf(sqrtf(ss), 1e-12f);
    v.x *= sc; v.y *= sc; v.z *= sc; v.w *= sc;
    reinterpret_cast<float4*>(dst)[lane] = v;
    __nv_bfloat162 p0 = __floats2bfloat162_rn(v.x, v.y);
    __nv_bfloat162 p1 = __floats2bfloat162_rn(v.z, v.w);
    uint2 w2 = make_uint2(*reinterpret_cast<uint32_t*>(&p0),
                          *reinterpret_cast<uint32_t*>(&p1));
    int ch = lane >> 1;
    int slot = (((ch ^ (rloc & 7)) << 1) | (lane & 1));
    bdst[slot] = w2;
}

// ---------------- K2: per-(j, quarter) masked key sums + count partials ----------------
__global__ void k_prep(const float* __restrict__ km, const float* __restrict__ qm) {
    __shared__ float kms[128];
    __shared__ float reda[4], redb[4];
    int b = blockIdx.x;
    int j = b >> 2, q = b & 3;
    int tid = threadIdx.x;
    int tbase = q * 128;
    float kmv = (km[j*SS + tbase + tid] > 0.999f) ? 1.0f : 0.0f;
    float qmv = qm[j*SS + tbase + tid];
    kms[tid] = kmv;
    __syncthreads();
    float acc = 0.0f;
    #pragma unroll 4
    for (int t = 0; t < 128; t++)
        acc += g_kn[((size_t)j*SS + tbase + t)*HH + tid] * kms[t];
    g_ksum4[(size_t)b*HH + tid] = acc;
    float a = kmv, b2 = qmv;
    #pragma unroll
    for (int off = 16; off >= 1; off >>= 1) {
        a  += __shfl_xor_sync(0xffffffffu, a, off);
        b2 += __shfl_xor_sync(0xffffffffu, b2, off);
    }
    if ((tid & 31) == 0) { reda[tid >> 5] = a; redb[tid >> 5] = b2; }
    __syncthreads();
    if (tid == 0) {
        g_cnt4[b*2 + 0] = reda[0]+reda[1]+reda[2]+reda[3];
        g_cnt4[b*2 + 1] = redb[0]+redb[1]+redb[2]+redb[3];
    }
    if (b == 0 && tid <= TT) g_wtab[tid] = expf(-0.5f * (float)tid);
}

// ---------------- K3: S1 + finalize counts ----------------
__global__ void k_s1() {
    __shared__ float ks[BB*HH];
    int tid = threadIdx.x;
    for (int x = tid; x < BB*HH; x += 256) {
        int jj = x >> 7, hh = x & (HH-1);
        float v = 0.f;
        #pragma unroll
        for (int p = 0; p < 4; p++) v += g_ksum4[((size_t)jj*4 + p)*HH + hh];
        ks[x] = v;
    }
    if (blockIdx.x == 0 && tid < BB) {
        float a = 0.f, b = 0.f;
        #pragma unroll
        for (int p = 0; p < 4; p++) { a += g_cnt4[(tid*4+p)*2+0]; b += g_cnt4[(tid*4+p)*2+1]; }
        g_kcnt[tid]   = a;
        g_qdenom[tid] = fmaxf(b, 1.0f);
    }
    __syncthreads();
    int w = tid >> 5, lane = tid & 31;
    int row = blockIdx.x * 8 + w;
    int i = row >> 9, s = row & (SS-1);
    float4 q = *reinterpret_cast<const float4*>(&g_qn[(size_t)row*HH + lane*4]);
    #pragma unroll
    for (int j = 0; j < BB; j++) {
        float4 k4 = *reinterpret_cast<const float4*>(&ks[j*HH + lane*4]);
        float p = q.x*k4.x + q.y*k4.y + q.z*k4.z + q.w*k4.w;
        #pragma unroll
        for (int off = 16; off >= 1; off >>= 1) p += __shfl_xor_sync(0xffffffffu, p, off);
        if (lane == 0) g_S1[((size_t)i*BB + j)*SS + s] = p;
    }
}

// ---------------- K4: main banded kernel — cp.async staging, 1 sync/ii ----------------
__global__ __launch_bounds__(256) void k_main(const float* __restrict__ qm,
                                              const float* __restrict__ km,
                                              float* __restrict__ out) {
    extern __shared__ char smem[];
    uint32_t sb = smem_u32(smem);
    int c = blockIdx.x, j = blockIdx.y, ig = blockIdx.z;
    int tid = threadIdx.x;
    int wid = tid >> 5, lane = tid & 31;
    int t0 = c*SC - TT;
    int s0 = c*SC;

    float* kmw = reinterpret_cast<float*>(smem + SM_KMW);
    float* wt  = reinterpret_cast<float*>(smem + SM_WT);
    float2* part = reinterpret_cast<float2*>(smem + SM_PART);   // [IGROUP][8][64]
    float2* s1q  = reinterpret_cast<float2*>(smem + SM_S1Q);    // [IGROUP][64]

    // stage K-window via cp.async (zfill out-of-range rows)
    for (int idx = tid; idx < TW*16; idx += 256) {
        int r = idx >> 4;
        int tg = t0 + r;
        bool ok = (tg >= 0 && tg < SS);
        const uint4* src = &g_kb[((size_t)j*SS + (ok ? tg : 0))*16 + (idx & 15)];
        cp_async16(sb + SM_A + idx*16, src, ok ? 16 : 0);
    }
    // stage Q buffer 0 via cp.async
    {
        int i0 = ig*IGROUP;
        for (int idx = tid; idx < SC*16; idx += 256)
            cp_async16(sb + SM_B + idx*16, &g_qb[((size_t)i0*SS + s0)*16 + idx], 16);
    }
    CP_COMMIT();
    if (tid < TW) { int tg = t0 + tid; kmw[tid] = (tg >= 0 && tg < SS) ? km[j*SS + tg] : 0.f; }
    if (tid >= 128 && tid <= 128+TT) wt[tid-128] = g_wtab[tid-128];
    // prefetch S1 + qm for all IGROUP i's
    for (int idx = tid; idx < IGROUP*SC; idx += 256) {
        int ii = idx >> 6, s = idx & 63;
        int i = ig*IGROUP + ii;
        s1q[idx] = make_float2(g_S1[((size_t)i*BB + j)*SS + s0 + s],
                               qm[i*SS + s0 + s]);
    }
    CP_WAIT0();
    __syncthreads();

    float kc_j = g_kcnt[j];
    int g_ = lane >> 2, t_ = lane & 3;
    int a_row = wid*16 + (lane & 15);
    int a_sel = lane >> 4;
    uint32_t a_rowoff = (uint32_t)(a_row * 256);
    int b_noff = ((lane >> 4) << 3) + (lane & 7);
    int b_sel = (lane >> 3) & 1;

    for (int ii = 0; ii < IGROUP; ii++) {
        int p = ii & 1;
        uint32_t bbase = sb + SM_B + (uint32_t)(p * 16384);

        // issue next-Q cp.async group FIRST (latency hides behind GEMM+epilogue)
        if (ii + 1 < IGROUP) {
            int inext = ig*IGROUP + ii + 1;
            uint32_t dst = sb + SM_B + (uint32_t)((1-p) * 16384);
            for (int idx = tid; idx < SC*16; idx += 256)
                cp_async16(dst + idx*16, &g_qb[((size_t)inext*SS + s0)*16 + idx], 16);
            CP_COMMIT();
        }

        // ---- GEMM ----
        float acc[8][4];
        #pragma unroll
        for (int nt = 0; nt < 8; nt++)
            #pragma unroll
            for (int x = 0; x < 4; x++) acc[nt][x] = 0.f;

        #pragma unroll
        for (int ks = 0; ks < 8; ks++) {
            int cb = 2*ks;
            uint32_t a_off = a_rowoff + (uint32_t)((((cb + a_sel) ^ (lane & 7)) << 4));
            uint32_t ah0,ah1,ah2,ah3;
            LDSM4(ah0,ah1,ah2,ah3, sb + SM_A + a_off);
            uint32_t b_chunk = (uint32_t)((((cb + b_sel) ^ (lane & 7)) << 4));
            #pragma unroll
            for (int np = 0; np < 4; np++) {
                uint32_t b_off = (uint32_t)((np*16 + b_noff) * 256) + b_chunk;
                uint32_t bh0,bh1,bh2,bh3;
                LDSM4(bh0,bh1,bh2,bh3, bbase + b_off);
                MMA16816(acc[2*np],   ah0,ah1,ah2,ah3, bh0,bh1);
                MMA16816(acc[2*np+1], ah0,ah1,ah2,ah3, bh2,bh3);
            }
        }

        // ---- epilogue (writes per-ii part region) ----
        int r0 = wid*16 + g_;
        int r1 = r0 + 8;
        bool kok0 = kmw[r0] > 0.999f;
        bool kok1 = kmw[r1] > 0.999f;
        float2* pii = part + ii*512 + wid*64;
        #pragma unroll
        for (int nt = 0; nt < 8; nt++) {
            int col0 = nt*8 + 2*t_;
            float gs0 = 0.f, gds0 = 0.f, gs1 = 0.f, gds1 = 0.f;
            {
                float d = acc[nt][0];
                int ad = r0 - col0 - TT; ad = (ad < 0) ? -ad : ad;
                if (ad <= TT && kok0) { float e = __expf(d * wt[ad]) - 1.0f; gs0 += e; gds0 += e*d; }
            }
            {
                float d = acc[nt][1];
                int ad = r0 - col0 - 1 - TT; ad = (ad < 0) ? -ad : ad;
                if (ad <= TT && kok0) { float e = __expf(d * wt[ad]) - 1.0f; gs1 += e; gds1 += e*d; }
            }
            {
                float d = acc[nt][2];
                int ad = r1 - col0 - TT; ad = (ad < 0) ? -ad : ad;
                if (ad <= TT && kok1) { float e = __expf(d * wt[ad]) - 1.0f; gs0 += e; gds0 += e*d; }
            }
            {
                float d = acc[nt][3];
                int ad = r1 - col0 - 1 - TT; ad = (ad < 0) ? -ad : ad;
                if (ad <= TT && kok1) { float e = __expf(d * wt[ad]) - 1.0f; gs1 += e; gds1 += e*d; }
            }
            #pragma unroll
            for (int off = 4; off <= 16; off <<= 1) {
                gs0  += __shfl_xor_sync(0xffffffffu, gs0,  off);
                gds0 += __shfl_xor_sync(0xffffffffu, gds0, off);
                gs1  += __shfl_xor_sync(0xffffffffu, gs1,  off);
                gds1 += __shfl_xor_sync(0xffffffffu, gds1, off);
            }
            if (g_ == 0) {
                pii[col0]     = make_float2(gs0, gds0);
                pii[col0 + 1] = make_float2(gs1, gds1);
            }
        }
        CP_WAIT0();        // next-Q group complete (usually already done)
        __syncthreads();   // Q buffer ready for next GEMM
    }

    // ---- deferred final: 512 (ii,s) items on 256 threads, 2 passes ----
    #pragma unroll
    for (int pass = 0; pass < 2; pass++) {
        int idx = pass*256 + tid;
        int ii = idx >> 6, s = idx & 63;
        float G = 0.f, Gd = 0.f;
        #pragma unroll
        for (int w = 0; w < 8; w++) {
            float2 p2 = part[ii*512 + w*64 + s];
            G += p2.x; Gd += p2.y;
        }
        float2 sq = s1q[ii*64 + s];
        float Z  = kc_j + G;
        float Nm = sq.x + Gd;
        float local = sq.y * ((Z > 1e-12f) ? (Nm / Z) : 0.f);
        #pragma unroll
        for (int off = 16; off >= 1; off >>= 1)
            local += __shfl_xor_sync(0xffffffffu, local, off);
        if (lane == 0) {
            int i = ig*IGROUP + ii;
            g_partial2[(((size_t)i*BB + j)*NC + c)*2 + (wid & 1)] = local;
        }
    }

    // ---- completion: last block reduces g_partial2 into out ----
    if (tid == 0) {
        __threadfence();
        int old = atomicAdd(&g_done, 1);
        *reinterpret_cast<int*>(smem + SM_FLAG) = (old == NBLOCKS - 1) ? 1 : 0;
    }
    __syncthreads();
    if (*reinterpret_cast<int*>(smem + SM_FLAG)) {
        __threadfence();
        int t = tid;                 // 256 = (i,j)
        float sacc = 0.f;
        #pragma unroll
        for (int cc = 0; cc < NC; cc++)
            sacc += g_partial2[((size_t)t*NC + cc)*2 + 0]
                  + g_partial2[((size_t)t*NC + cc)*2 + 1];
        out[t] = sacc / g_qdenom[t >> 4];
    }
}

// ---------------- launch ----------------
extern "C" void kernel_launch(void* const* d_in, const int* in_sizes, int n_in,
                              void* d_out, int out_size) {
    const float* qe = (const float*)d_in[0];
    const float* ke = (const float*)d_in[1];
    const float* qm = (const float*)d_in[2];
    const float* km = (const float*)d_in[3];
    float* out = (float*)d_out;

    cudaFuncSetAttribute(k_main, cudaFuncAttributeMaxDynamicSharedMemorySize, SMEM_TOTAL);

    k_norm <<<(2*BB*SS)/8, 256>>>(qe, ke);
    k_prep <<<BB*4, 128>>>(km, qm);
    k_s1   <<<(BB*SS)/8, 256>>>();
    k_main <<<dim3(NC, BB, BB/IGROUP), 256, SMEM_TOTAL>>>(qm, km, out);
}